// round 2
// baseline (speedup 1.0000x reference)
#include <cuda_runtime.h>
#include <cuda_bf16.h>
#include <math.h>

// ---------------- problem constants ----------------
#define Bb 16
#define NH 8
#define BH (Bb*NH)          // 128
#define Hh 56
#define Ww 56
#define Nn (Hh*Ww)          // 3136
#define HD 64
#define RATIO 4
#define HL (Hh/RATIO)       // 14
#define MM (HL*HL)          // 196 landmarks
#define PATCH (RATIO*RATIO*HD) // 1024
#define NEWTON_ITERS 20
#define LN_EPS 1e-5f
#define QSCALE 0.35355339059327373f   // 64^{-0.25}

// ---------------- device scratch (no cudaMalloc allowed) ----------------
__device__ float g_Qs   [(size_t)BH*Nn*HD];      // scaled Q
__device__ float g_qn   [(size_t)BH*Nn];         // |q_i|^2
__device__ float g_patch[(size_t)BH*MM*PATCH];   // im2col for landmark conv
__device__ float g_Ql   [(size_t)BH*MM*HD];      // landmarks (pre -> post LN/GELU in place)
__device__ float g_QlT  [(size_t)BH*HD*MM];      // transposed landmarks
__device__ float g_ln   [(size_t)BH*MM];         // |Ql_j|^2
__device__ float g_k2   [(size_t)BH*MM*MM];      // P
__device__ float g_scale[BH];                    // 1/(n1*ninf)
__device__ float g_Va   [(size_t)BH*MM*MM];
__device__ float g_Vb   [(size_t)BH*MM*MM];
__device__ float g_T    [(size_t)BH*MM*MM];
__device__ float g_k1   [(size_t)BH*Nn*MM];      // big gauss kernel
__device__ float g_Z    [(size_t)BH*MM*HD];
__device__ float g_Y    [(size_t)BH*MM*HD];

// ---------------- kernel 1: Qs = Q*s, qn = |row|^2 ----------------
__global__ __launch_bounds__(256) void scale_qnorm_kernel(const float* __restrict__ Q,
                                                          float* __restrict__ Qs,
                                                          float* __restrict__ qn) {
    size_t warp = ((size_t)blockIdx.x * blockDim.x + threadIdx.x) >> 5;
    int lane = threadIdx.x & 31;
    if (warp >= (size_t)BH * Nn) return;
    float2 v = ((const float2*)(Q + warp * HD))[lane];
    v.x *= QSCALE; v.y *= QSCALE;
    ((float2*)(Qs + warp * HD))[lane] = v;
    float ss = v.x * v.x + v.y * v.y;
    #pragma unroll
    for (int o = 16; o; o >>= 1) ss += __shfl_xor_sync(0xffffffffu, ss, o);
    if (lane == 0) qn[warp] = ss;
}

// ---------------- kernel 2: im2col (exact, H divisible by RATIO) ----------------
__global__ __launch_bounds__(256) void im2col_kernel(const float* __restrict__ Qs,
                                                     float* __restrict__ patch) {
    size_t idx = (size_t)blockIdx.x * blockDim.x + threadIdx.x;
    const size_t total = (size_t)BH * MM * PATCH;
    if (idx >= total) return;
    int ic = idx & (HD - 1);
    int e  = (int)((idx >> 6) & 15);        // dy*4+dx
    size_t row = idx >> 10;                 // bh*196 + p
    int p  = (int)(row % MM);
    int bh = (int)(row / MM);
    int py = p / HL, px = p % HL;
    int dy = e >> 2, dx = e & 3;
    int y = py * RATIO + dy, x = px * RATIO + dx;
    patch[idx] = Qs[((size_t)bh * Nn + (size_t)y * Ww + x) * HD + ic];
}

// ---------------- generic batched tiled SGEMM ----------------
// EPI: 0 C=AB, 1 C=exp(-0.5(r[i]+c[j]-2AB)), 2 C=2A-AB (square), 3 C+=AB
// TRA: 0 A is [M,K] lda=K-ish; 1 A stored [K,M], compute A^T B
#define BMt 64
#define BNt 64
#define BKt 16
template<int EPI, int TRA>
__global__ __launch_bounds__(256) void gemm_kernel(const float* __restrict__ A,
                                                   const float* __restrict__ B,
                                                   float* __restrict__ C,
                                                   const float* __restrict__ rAux,
                                                   const float* __restrict__ cAux,
                                                   int M, int N, int K,
                                                   int lda, int ldb, int ldc,
                                                   size_t sA, size_t sB, size_t sC,
                                                   int sRA, int sCA) {
    int bz = blockIdx.z;
    A += (size_t)bz * sA; B += (size_t)bz * sB; C += (size_t)bz * sC;
    if (EPI == 1) { rAux += (size_t)bz * sRA; cAux += (size_t)bz * sCA; }
    int m0 = blockIdx.y * BMt, n0 = blockIdx.x * BNt;
    __shared__ float As[BKt][BMt];
    __shared__ float Bs[BKt][BNt];
    int t = threadIdx.x;
    int tx = t & 15, ty = t >> 4;
    float acc[4][4] = {};
    for (int k0 = 0; k0 < K; k0 += BKt) {
        #pragma unroll
        for (int j = 0; j < 4; j++) {
            int idx = t + 256 * j;
            if (TRA == 0) {
                int kk = idx & 15, mm = idx >> 4;
                int gm = m0 + mm, gk = k0 + kk;
                As[kk][mm] = (gm < M && gk < K) ? A[(size_t)gm * lda + gk] : 0.f;
            } else {
                int mm = idx & 63, kk = idx >> 6;
                int gm = m0 + mm, gk = k0 + kk;
                As[kk][mm] = (gm < M && gk < K) ? A[(size_t)gk * lda + gm] : 0.f;
            }
            int nn = idx & 63, kk2 = idx >> 6;
            int gn = n0 + nn, gk2 = k0 + kk2;
            Bs[kk2][nn] = (gn < N && gk2 < K) ? B[(size_t)gk2 * ldb + gn] : 0.f;
        }
        __syncthreads();
        #pragma unroll
        for (int kk = 0; kk < BKt; kk++) {
            float a[4], b[4];
            #pragma unroll
            for (int i = 0; i < 4; i++) a[i] = As[kk][ty * 4 + i];
            #pragma unroll
            for (int j = 0; j < 4; j++) b[j] = Bs[kk][tx * 4 + j];
            #pragma unroll
            for (int i = 0; i < 4; i++)
                #pragma unroll
                for (int j = 0; j < 4; j++)
                    acc[i][j] += a[i] * b[j];
        }
        __syncthreads();
    }
    #pragma unroll
    for (int i = 0; i < 4; i++) {
        int gm = m0 + ty * 4 + i;
        if (gm >= M) continue;
        #pragma unroll
        for (int j = 0; j < 4; j++) {
            int gn = n0 + tx * 4 + j;
            if (gn >= N) continue;
            float v = acc[i][j];
            size_t off = (size_t)gm * ldc + gn;
            if (EPI == 0)      C[off] = v;
            else if (EPI == 1) C[off] = __expf(-0.5f * (rAux[gm] + cAux[gn] - 2.f * v));
            else if (EPI == 2) C[off] = 2.f * A[(size_t)gm * lda + gn] - v;
            else               C[off] += v;
        }
    }
}

// ---------------- kernel: LayerNorm + erf-GELU + transpose + norms ----------------
__global__ __launch_bounds__(64) void ln_gelu_kernel(float* __restrict__ Ql,
                                                     float* __restrict__ QlT,
                                                     float* __restrict__ lnn,
                                                     const float* __restrict__ gamma,
                                                     const float* __restrict__ beta) {
    int row = blockIdx.x;        // bh*196 + p
    int t = threadIdx.x;         // 64
    __shared__ float sm[2];
    float x = Ql[(size_t)row * HD + t];

    float v = x;
    #pragma unroll
    for (int o = 16; o; o >>= 1) v += __shfl_xor_sync(0xffffffffu, v, o);
    if ((t & 31) == 0) sm[t >> 5] = v;
    __syncthreads();
    float mean = (sm[0] + sm[1]) * (1.f / HD);
    __syncthreads();

    float d = x - mean;
    v = d * d;
    #pragma unroll
    for (int o = 16; o; o >>= 1) v += __shfl_xor_sync(0xffffffffu, v, o);
    if ((t & 31) == 0) sm[t >> 5] = v;
    __syncthreads();
    float var = (sm[0] + sm[1]) * (1.f / HD);
    __syncthreads();

    float y = d * rsqrtf(var + LN_EPS) * gamma[t] + beta[t];
    float g = 0.5f * y * (1.f + erff(y * 0.70710678118654752f));

    Ql[(size_t)row * HD + t] = g;
    int bh = row / MM, p = row % MM;
    QlT[((size_t)bh * HD + t) * MM + p] = g;

    v = g * g;
    #pragma unroll
    for (int o = 16; o; o >>= 1) v += __shfl_xor_sync(0xffffffffu, v, o);
    if ((t & 31) == 0) sm[t >> 5] = v;
    __syncthreads();
    if (t == 0) lnn[row] = sm[0] + sm[1];
}

// ---------------- kernel: per-batch 1/(n1*ninf) (symmetric -> maxRowSum^2) ----------------
__global__ __launch_bounds__(256) void nscale_kernel(const float* __restrict__ k2,
                                                     float* __restrict__ scale) {
    int bh = blockIdx.x;
    int t = threadIdx.x;
    float rs = 0.f;
    if (t < MM) {
        const float* r = k2 + (size_t)bh * MM * MM + (size_t)t * MM;
        for (int j = 0; j < MM; j++) rs += r[j];
    }
    __shared__ float sm[256];
    sm[t] = rs;
    __syncthreads();
    for (int o = 128; o; o >>= 1) {
        if (t < o) sm[t] = fmaxf(sm[t], sm[t + o]);
        __syncthreads();
    }
    if (t == 0) scale[bh] = 1.f / (sm[0] * sm[0]);
}

// ---------------- kernel: V0 = P * scale (symmetric so P^T == P) ----------------
__global__ __launch_bounds__(256) void v0_kernel(const float* __restrict__ k2,
                                                 const float* __restrict__ scale,
                                                 float* __restrict__ V0) {
    size_t i = (size_t)blockIdx.x * blockDim.x + threadIdx.x;
    const size_t total = (size_t)BH * MM * MM;
    if (i >= total) return;
    V0[i] = k2[i] * scale[i / ((size_t)MM * MM)];
}

// ---------------- kernel: depthwise 3x3 conv over heads, writes d_out ----------------
__global__ __launch_bounds__(256) void dwconv_kernel(const float* __restrict__ V,
                                                     const float* __restrict__ w,
                                                     float* __restrict__ out) {
    int bh = blockIdx.y;
    int y  = blockIdx.x;
    int h  = bh & (NH - 1);
    float wv[9];
    #pragma unroll
    for (int k = 0; k < 9; k++) wv[k] = w[k * NH + h];   // conv_w [3,3,1,NH]
    for (int idx = threadIdx.x; idx < Ww * HD; idx += blockDim.x) {
        int x = idx >> 6;
        int c = idx & (HD - 1);
        float acc = 0.f;
        #pragma unroll
        for (int dy = -1; dy <= 1; dy++) {
            int yy = y + dy;
            if (yy < 0 || yy >= Hh) continue;
            #pragma unroll
            for (int dx = -1; dx <= 1; dx++) {
                int xx = x + dx;
                if (xx < 0 || xx >= Ww) continue;
                acc += wv[(dy + 1) * 3 + (dx + 1)] *
                       V[((size_t)bh * Nn + (size_t)yy * Ww + xx) * HD + c];
            }
        }
        out[((size_t)bh * Nn + (size_t)y * Ww + x) * HD + c] = acc;
    }
}

// ---------------- host launch ----------------
static inline int ceil_div(int a, int b) { return (a + b - 1) / b; }

extern "C" void kernel_launch(void* const* d_in, const int* in_sizes, int n_in,
                              void* d_out, int out_size) {
    const float* Q      = (const float*)d_in[0];
    const float* V      = (const float*)d_in[1];
    const float* w_land = (const float*)d_in[2];
    const float* gamma  = (const float*)d_in[3];
    const float* beta   = (const float*)d_in[4];
    const float* conv_w = (const float*)d_in[5];
    float* out = (float*)d_out;

    float *Qs, *qn, *patch, *Ql, *QlT, *lnn, *k2, *scale, *Va, *Vb, *T, *k1, *Z, *Y;
    cudaGetSymbolAddress((void**)&Qs,    g_Qs);
    cudaGetSymbolAddress((void**)&qn,    g_qn);
    cudaGetSymbolAddress((void**)&patch, g_patch);
    cudaGetSymbolAddress((void**)&Ql,    g_Ql);
    cudaGetSymbolAddress((void**)&QlT,   g_QlT);
    cudaGetSymbolAddress((void**)&lnn,   g_ln);
    cudaGetSymbolAddress((void**)&k2,    g_k2);
    cudaGetSymbolAddress((void**)&scale, g_scale);
    cudaGetSymbolAddress((void**)&Va,    g_Va);
    cudaGetSymbolAddress((void**)&Vb,    g_Vb);
    cudaGetSymbolAddress((void**)&T,     g_T);
    cudaGetSymbolAddress((void**)&k1,    g_k1);
    cudaGetSymbolAddress((void**)&Z,     g_Z);
    cudaGetSymbolAddress((void**)&Y,     g_Y);

    // 1) scale + row norms
    {
        size_t rows = (size_t)BH * Nn;
        int blocks = (int)((rows * 32 + 255) / 256);
        scale_qnorm_kernel<<<blocks, 256>>>(Q, Qs, qn);
    }
    // 2) im2col
    {
        size_t total = (size_t)BH * MM * PATCH;
        im2col_kernel<<<(int)((total + 255) / 256), 256>>>(Qs, patch);
    }
    // 3) landmark conv as single GEMM: [25088,1024]x[1024,64]
    {
        dim3 grid(ceil_div(HD, BNt), ceil_div(BH * MM, BMt), 1);
        gemm_kernel<0, 0><<<grid, 256>>>(patch, w_land, Ql, nullptr, nullptr,
                                         BH * MM, HD, PATCH, PATCH, HD, HD,
                                         0, 0, 0, 0, 0);
    }
    // 4) LN + GELU + transpose + norms
    ln_gelu_kernel<<<BH * MM, 64>>>(Ql, QlT, lnn, gamma, beta);
    // 5) k2 = gauss(Ql,Ql): exp-epilogue GEMM, batched
    {
        dim3 grid(ceil_div(MM, BNt), ceil_div(MM, BMt), BH);
        gemm_kernel<1, 0><<<grid, 256>>>(Ql, QlT, k2, lnn, lnn,
                                         MM, MM, HD, HD, MM, MM,
                                         (size_t)MM * HD, (size_t)HD * MM, (size_t)MM * MM,
                                         MM, MM);
    }
    // 6) Newton init scale + V0
    nscale_kernel<<<BH, 256>>>(k2, scale);
    {
        size_t total = (size_t)BH * MM * MM;
        v0_kernel<<<(int)((total + 255) / 256), 256>>>(k2, scale, Va);
    }
    // 7) Newton-Schulz: 20 iterations, ping-pong
    {
        dim3 grid(ceil_div(MM, BNt), ceil_div(MM, BMt), BH);
        float* cur = Va;
        float* nxt = Vb;
        for (int it = 0; it < NEWTON_ITERS; it++) {
            gemm_kernel<0, 0><<<grid, 256>>>(k2, cur, T, nullptr, nullptr,
                                             MM, MM, MM, MM, MM, MM,
                                             (size_t)MM * MM, (size_t)MM * MM, (size_t)MM * MM,
                                             0, 0);
            gemm_kernel<2, 0><<<grid, 256>>>(cur, T, nxt, nullptr, nullptr,
                                             MM, MM, MM, MM, MM, MM,
                                             (size_t)MM * MM, (size_t)MM * MM, (size_t)MM * MM,
                                             0, 0);
            float* tmp = cur; cur = nxt; nxt = tmp;
        }
        // after even count, cur == Va
    }
    // 8) k1 = gauss(Qs, Ql): [3136,64]x[64,196] batched + exp epilogue
    {
        dim3 grid(ceil_div(MM, BNt), ceil_div(Nn, BMt), BH);
        gemm_kernel<1, 0><<<grid, 256>>>(Qs, QlT, k1, qn, lnn,
                                         Nn, MM, HD, HD, MM, MM,
                                         (size_t)Nn * HD, (size_t)HD * MM, (size_t)Nn * MM,
                                         Nn, MM);
    }
    // 9) Z = k1^T @ V  (TRA=1): M=196, N=64, K=3136
    {
        dim3 grid(ceil_div(HD, BNt), ceil_div(MM, BMt), BH);
        gemm_kernel<0, 1><<<grid, 256>>>(k1, V, Z, nullptr, nullptr,
                                         MM, HD, Nn, MM, HD, HD,
                                         (size_t)Nn * MM, (size_t)Nn * HD, (size_t)MM * HD,
                                         0, 0);
    }
    // 10) Y = inv @ Z: M=196, N=64, K=196
    {
        dim3 grid(ceil_div(HD, BNt), ceil_div(MM, BMt), BH);
        gemm_kernel<0, 0><<<grid, 256>>>(Va, Z, Y, nullptr, nullptr,
                                         MM, HD, MM, MM, HD, HD,
                                         (size_t)MM * MM, (size_t)MM * HD, (size_t)MM * HD,
                                         0, 0);
    }
    // 11) depthwise conv residual -> d_out
    {
        dim3 grid(Hh, BH);
        dwconv_kernel<<<grid, 256>>>(V, conv_w, out);
    }
    // 12) d_out += k1 @ Y: M=3136, N=64, K=196
    {
        dim3 grid(ceil_div(HD, BNt), ceil_div(Nn, BMt), BH);
        gemm_kernel<3, 0><<<grid, 256>>>(k1, Y, out, nullptr, nullptr,
                                         Nn, HD, MM, MM, HD, HD,
                                         (size_t)Nn * MM, (size_t)MM * HD, (size_t)Nn * HD,
                                         0, 0);
    }
    (void)in_sizes; (void)n_in; (void)out_size;
}